// round 1
// baseline (speedup 1.0000x reference)
#include <cuda_runtime.h>
#include <math.h>

// Problem constants (fixed by the reference)
#define NU 8192
#define NI 8192
#define D 32
#define KC 32
#define NH 4
#define HK 8
#define BIASF 0.1f

#define KB 128   // blocks for keys kernel  (NU / KT)
#define KT 64    // rows (threads) per keys block
#define IB 128   // blocks for items kernel (NI / IT)
#define IT 64    // items (threads) per item block

// Scratch: __device__ globals (no allocation allowed).
// All of these are fully overwritten every launch -> graph-replay safe.
__device__ float g_logits[NU * KC];   // keys logits (for the honest fallback path)
__device__ float g_pmax[KB * KC];     // per-block partial column max(logit)
__device__ float g_psum[KB * KC];     // per-block partial column sum(exp(logit))
__device__ float g_invZ[KC];          // 1 / Z_c
__device__ float g_colmaxw[KC];       // max_u softmax weight per column = exp(max)/Z

// ---------------------------------------------------------------------------
// Kernel 1: keys = U @ keys_w + keys_b ; store logits; partial column max/sumexp
// ---------------------------------------------------------------------------
__global__ void __launch_bounds__(KT) k_keys(const float* __restrict__ U,
                                             const float* __restrict__ Kw,
                                             const float* __restrict__ Kb)
{
    __shared__ float sW[D * KC];
    __shared__ float sB[KC];
    __shared__ float red[4 * KC];   // [warp0 max|warp0 sum|warp1 max|warp1 sum]

    int t = threadIdx.x;
    for (int i = t; i < D * KC; i += KT) sW[i] = Kw[i];
    if (t < KC) sB[t] = Kb[t];
    __syncthreads();

    int row = blockIdx.x * KT + t;

    float u[D];
    const float4* up = (const float4*)(U + (size_t)row * D);
#pragma unroll
    for (int i = 0; i < D / 4; i++) {
        float4 v = up[i];
        u[4*i+0] = v.x; u[4*i+1] = v.y; u[4*i+2] = v.z; u[4*i+3] = v.w;
    }

    float l[KC];
#pragma unroll
    for (int c = 0; c < KC; c++) {
        float acc = sB[c];
#pragma unroll
        for (int d = 0; d < D; d++) acc = fmaf(u[d], sW[d * KC + c], acc);
        l[c] = acc;
    }

    float4* lp = (float4*)(g_logits + (size_t)row * KC);
#pragma unroll
    for (int i = 0; i < KC / 4; i++)
        lp[i] = make_float4(l[4*i+0], l[4*i+1], l[4*i+2], l[4*i+3]);

    // Per-column reduction across the block: max(logit), sum(exp(logit)).
    // Logits here are tiny (|l| < ~4), so unshifted exp is numerically safe.
    int warp = t >> 5;
#pragma unroll
    for (int c = 0; c < KC; c++) {
        float m = l[c];
        float s = __expf(l[c]);
#pragma unroll
        for (int o = 16; o > 0; o >>= 1) {
            m = fmaxf(m, __shfl_xor_sync(0xffffffffu, m, o));
            s += __shfl_xor_sync(0xffffffffu, s, o);
        }
        if ((t & 31) == 0) {
            red[warp * 2 * KC + c]      = m;
            red[warp * 2 * KC + KC + c] = s;
        }
    }
    __syncthreads();
    if (t < KC) {
        float m = fmaxf(red[t], red[2 * KC + t]);
        float s = red[KC + t] + red[3 * KC + t];
        g_pmax[blockIdx.x * KC + t] = m;
        g_psum[blockIdx.x * KC + t] = s;
    }
}

// ---------------------------------------------------------------------------
// Kernel 2: fold partials -> invZ, colmaxw
// ---------------------------------------------------------------------------
__global__ void k_reduce()
{
    int c = threadIdx.x;
    if (c < KC) {
        float m = -3.0e38f, s = 0.0f;
        for (int b = 0; b < KB; b++) {
            m = fmaxf(m, g_pmax[b * KC + c]);
            s += g_psum[b * KC + c];
        }
        g_invZ[c]    = 1.0f / s;
        g_colmaxw[c] = __expf(m) / s;   // exact max softmax weight in column c
    }
}

// ---------------------------------------------------------------------------
// Kernel 3: per-item queries + softmax + rigorous upper bound; fast path writes
// out = I + reproj_b; slow path does the full honest attention for the tile.
// ---------------------------------------------------------------------------
__global__ void __launch_bounds__(IT) k_items(const float* __restrict__ Iemb,
                                              const float* __restrict__ Qw,
                                              const float* __restrict__ Qb,
                                              const float* __restrict__ U,
                                              const float* __restrict__ Rw,
                                              const float* __restrict__ Rb,
                                              float* __restrict__ out)
{
    __shared__ float sW[D * KC];
    __shared__ float sB[KC];
    __shared__ float sCM[KC];
    __shared__ float sRb[KC];
    __shared__ float sIZ[KC];

    int t = threadIdx.x;
    for (int i = t; i < D * KC; i += IT) sW[i] = Qw[i];
    if (t < KC) {
        sB[t]  = Qb[t];
        sCM[t] = g_colmaxw[t];
        sRb[t] = Rb[t];
        sIZ[t] = g_invZ[t];
    }
    __syncthreads();

    int item = blockIdx.x * IT + t;

    float e[D];
    const float4* ip = (const float4*)(Iemb + (size_t)item * D);
#pragma unroll
    for (int i = 0; i < D / 4; i++) {
        float4 v = ip[i];
        e[4*i+0] = v.x; e[4*i+1] = v.y; e[4*i+2] = v.z; e[4*i+3] = v.w;
    }

    // queries logits
    float ql[KC];
#pragma unroll
    for (int c = 0; c < KC; c++) {
        float acc = sB[c];
#pragma unroll
        for (int d = 0; d < D; d++) acc = fmaf(e[d], sW[d * KC + c], acc);
        ql[c] = acc;
    }

    // per-head softmax over 8 channels
    float q[KC];
#pragma unroll
    for (int h = 0; h < NH; h++) {
        float m = ql[h * HK];
#pragma unroll
        for (int c = 1; c < HK; c++) m = fmaxf(m, ql[h * HK + c]);
        float s = 0.0f;
#pragma unroll
        for (int c = 0; c < HK; c++) {
            float v = __expf(ql[h * HK + c] - m);
            q[h * HK + c] = v;
            s += v;
        }
        float inv = 1.0f / s;
#pragma unroll
        for (int c = 0; c < HK; c++) q[h * HK + c] *= inv;
    }

    // Rigorous bound: dot(u) <= sum_c q_c * max_u k[u,c]  (q >= 0).
    int heavy = 0;
#pragma unroll
    for (int h = 0; h < NH; h++) {
        float ub = 0.0f;
#pragma unroll
        for (int c = 0; c < HK; c++) ub += q[h * HK + c] * sCM[h * HK + c];
        heavy |= (ub > BIASF);
    }

    if (!__syncthreads_or(heavy)) {
        // FAST PATH: ctx == 0 for every (u, head) of every item in this tile
        //   => att = 0 => proj = reproj_b => out = I + reproj_b  (exact).
        float4* op = (float4*)(out + (size_t)item * KC);
#pragma unroll
        for (int i = 0; i < KC / 4; i++)
            op[i] = make_float4(e[4*i+0] + sRb[4*i+0], e[4*i+1] + sRb[4*i+1],
                                e[4*i+2] + sRb[4*i+2], e[4*i+3] + sRb[4*i+3]);
        return;
    }

    // SLOW PATH (block-uniform; correctness fallback — not expected to run).
    __shared__ float sK[64][KC];
    __shared__ float sU[64][D];

    float att[NH][D];
#pragma unroll
    for (int h = 0; h < NH; h++)
#pragma unroll
        for (int d = 0; d < D; d++) att[h][d] = 0.0f;

    for (int u0 = 0; u0 < NU; u0 += 64) {
        __syncthreads();
        for (int i = t; i < 64 * KC; i += IT) {
            int r = i >> 5, c = i & 31;
            sK[r][c] = __expf(g_logits[(size_t)(u0 + r) * KC + c]) * sIZ[c];
        }
        for (int i = t; i < 64 * D; i += IT) {
            int r = i >> 5, c = i & 31;
            sU[r][c] = U[(size_t)(u0 + r) * D + c];
        }
        __syncthreads();

        for (int u = 0; u < 64; u++) {
#pragma unroll
            for (int h = 0; h < NH; h++) {
                float dot = 0.0f;
#pragma unroll
                for (int c = 0; c < HK; c++) dot += sK[u][h * HK + c] * q[h * HK + c];
                float w = dot - BIASF;
                if (w > 0.0f) {
#pragma unroll
                    for (int d = 0; d < D; d++) att[h][d] += w * sU[u][d];
                }
            }
        }
    }

    // reprojection: agg[h*32+d] -> out
    float o[D];
#pragma unroll
    for (int j = 0; j < D; j++) o[j] = sRb[j];
    for (int m = 0; m < NH * D; m++) {
        float a = att[m >> 5][m & 31];
#pragma unroll
        for (int j = 0; j < D; j++) o[j] += a * Rw[m * KC + j];
    }
#pragma unroll
    for (int j = 0; j < D; j++) out[(size_t)item * KC + j] = e[j] + o[j];
}

// ---------------------------------------------------------------------------
extern "C" void kernel_launch(void* const* d_in, const int* in_sizes, int n_in,
                              void* d_out, int out_size)
{
    (void)in_sizes; (void)n_in; (void)out_size;
    const float* U  = (const float*)d_in[0];
    const float* I  = (const float*)d_in[1];
    const float* Kw = (const float*)d_in[2];
    const float* Kb = (const float*)d_in[3];
    const float* Qw = (const float*)d_in[4];
    const float* Qb = (const float*)d_in[5];
    const float* Rw = (const float*)d_in[6];
    const float* Rb = (const float*)d_in[7];
    float* out = (float*)d_out;

    k_keys<<<KB, KT>>>(U, Kw, Kb);
    k_reduce<<<1, 32>>>();
    k_items<<<IB, IT>>>(I, Qw, Qb, U, Rw, Rb, out);
}

// round 3
// speedup vs baseline: 1.6804x; 1.6804x over previous
#include <cuda_runtime.h>
#include <math.h>

// Problem constants (fixed by the reference)
#define NU 8192
#define NI 8192
#define D 32
#define KC 32
#define NH 4
#define HK 8
#define BIASF 0.1f

#define NB 128     // blocks per kernel
#define NT 128     // threads per block
#define RPB 64     // rows/items per block (2 threads per row)

// Scratch (__device__ globals; no allocation allowed). All graph-replay safe:
// g_ctr is reset in-kernel by the folding block every launch.
__device__ float g_pmax[NB * KC];   // per-block partial column max(exp(logit))
__device__ float g_psum[NB * KC];   // per-block partial column sum(exp(logit))
__device__ float g_cm[KC];          // max softmax weight per column = maxexp/Z
__device__ float g_iz[KC];          // 1/Z per column
__device__ unsigned g_ctr;          // "last block" counter

// ---------------------------------------------------------------------------
// Kernel A: keys logits -> exp -> column partials; last block folds to g_cm/g_iz
// ---------------------------------------------------------------------------
__global__ void __launch_bounds__(NT) k_keys(const float* __restrict__ U,
                                             const float* __restrict__ Kw,
                                             const float* __restrict__ Kb)
{
    __shared__ float sWT[KC][D];        // transposed weights: sWT[c][d]
    __shared__ float sB[KC];
    __shared__ float sExp[RPB][KC + 1]; // +1 pad: conflict-free strided writes
    __shared__ float sRed[2][4][KC];
    __shared__ int   sLast;

    const int t = threadIdx.x;
    for (int i = t; i < D * KC; i += NT) sWT[i & 31][i >> 5] = Kw[i];
    if (t < KC) sB[t] = Kb[t];
    __syncthreads();

    const int r = t >> 1, half = t & 1;
    const int row = blockIdx.x * RPB + r;

    float u[D];
    {
        const float4* up = (const float4*)(U + (size_t)row * D);
#pragma unroll
        for (int i = 0; i < 8; i++) {
            float4 v = up[i];
            u[4*i] = v.x; u[4*i+1] = v.y; u[4*i+2] = v.z; u[4*i+3] = v.w;
        }
    }

    const int c0 = half * 16;
#pragma unroll
    for (int cc = 0; cc < 16; cc++) {
        const int c = c0 + cc;
        float acc = sB[c];
        const float4* wp = (const float4*)&sWT[c][0];
#pragma unroll
        for (int i = 0; i < 8; i++) {
            float4 w = wp[i];
            acc = fmaf(u[4*i+0], w.x, acc);
            acc = fmaf(u[4*i+1], w.y, acc);
            acc = fmaf(u[4*i+2], w.z, acc);
            acc = fmaf(u[4*i+3], w.w, acc);
        }
        // logits tiny (|l| < ~4) -> unshifted exp is safe; exp is monotone so
        // column max of exp == exp of column max.
        sExp[r][c] = __expf(acc);
    }
    __syncthreads();

    // Transpose reduction: thread (c = t&31, qtr = t>>5) reduces 16 rows.
    {
        const int c = t & 31, qtr = t >> 5;
        float m = 0.0f, s = 0.0f;
#pragma unroll
        for (int rr = 0; rr < 16; rr++) {
            float v = sExp[qtr * 16 + rr][c];
            m = fmaxf(m, v); s += v;
        }
        sRed[0][qtr][c] = m; sRed[1][qtr][c] = s;
    }
    __syncthreads();
    if (t < KC) {
        float m = fmaxf(fmaxf(sRed[0][0][t], sRed[0][1][t]),
                        fmaxf(sRed[0][2][t], sRed[0][3][t]));
        float s = sRed[1][0][t] + sRed[1][1][t] + sRed[1][2][t] + sRed[1][3][t];
        g_pmax[blockIdx.x * KC + t] = m;
        g_psum[blockIdx.x * KC + t] = s;
    }
    __threadfence();          // publish partials (device scope)
    __syncthreads();
    if (t == 0) sLast = (atomicAdd(&g_ctr, 1u) == (unsigned)(NB - 1));
    __syncthreads();
    if (!sLast) return;       // no spinning: non-last blocks exit

    // Last arriving block folds all partials (L2-resident) -> g_cm, g_iz.
    {
        const int c = t & 31, qtr = t >> 5;
        float m = 0.0f, s = 0.0f;
        for (int b = qtr * 32; b < qtr * 32 + 32; b++) {
            m = fmaxf(m, __ldcg(&g_pmax[b * KC + c]));
            s += __ldcg(&g_psum[b * KC + c]);
        }
        sRed[0][qtr][c] = m; sRed[1][qtr][c] = s;
    }
    __syncthreads();
    if (t < KC) {
        float m = fmaxf(fmaxf(sRed[0][0][t], sRed[0][1][t]),
                        fmaxf(sRed[0][2][t], sRed[0][3][t]));
        float s = sRed[1][0][t] + sRed[1][1][t] + sRed[1][2][t] + sRed[1][3][t];
        g_cm[t] = m / s;      // exact max softmax weight in column t
        g_iz[t] = 1.0f / s;
    }
    if (t == 0) g_ctr = 0u;   // reset for next launch / graph replay
}

// ---------------------------------------------------------------------------
// Kernel B: items. 2 threads per item (16 columns = 2 heads each).
// ---------------------------------------------------------------------------
__global__ void __launch_bounds__(NT) k_items(const float* __restrict__ Iemb,
                                              const float* __restrict__ Qw,
                                              const float* __restrict__ Qb,
                                              const float* __restrict__ U,
                                              const float* __restrict__ Kw,
                                              const float* __restrict__ Kb,
                                              const float* __restrict__ Rw,
                                              const float* __restrict__ Rb,
                                              float* __restrict__ out)
{
    __shared__ float sWT[KC][D];       // transposed query weights
    __shared__ float sB[KC];
    __shared__ float sCM[KC], sRb[KC], sIZ[KC];

    const int t = threadIdx.x;
    for (int i = t; i < D * KC; i += NT) sWT[i & 31][i >> 5] = Qw[i];
    if (t < KC) { sB[t] = Qb[t]; sCM[t] = g_cm[t]; sRb[t] = Rb[t]; sIZ[t] = g_iz[t]; }
    __syncthreads();

    const int r = t >> 1, half = t & 1;
    const int item = blockIdx.x * RPB + r;
    const int c0 = half * 16;

    float e[D];
    {
        const float4* ip = (const float4*)(Iemb + (size_t)item * D);
#pragma unroll
        for (int i = 0; i < 8; i++) {
            float4 v = ip[i];
            e[4*i] = v.x; e[4*i+1] = v.y; e[4*i+2] = v.z; e[4*i+3] = v.w;
        }
    }

    // query logits for this thread's 16 columns (2 heads)
    float q[16];
#pragma unroll
    for (int cc = 0; cc < 16; cc++) {
        const int c = c0 + cc;
        float acc = sB[c];
        const float4* wp = (const float4*)&sWT[c][0];
#pragma unroll
        for (int i = 0; i < 8; i++) {
            float4 w = wp[i];
            acc = fmaf(e[4*i+0], w.x, acc);
            acc = fmaf(e[4*i+1], w.y, acc);
            acc = fmaf(e[4*i+2], w.z, acc);
            acc = fmaf(e[4*i+3], w.w, acc);
        }
        q[cc] = acc;
    }

    // per-head softmax (8 channels each), then rigorous upper bound:
    // dot(u) <= sum_c q_c * max_u k[u,c]  (q >= 0, sum q = 1 per head)
    int heavy = 0;
#pragma unroll
    for (int hh = 0; hh < 2; hh++) {
        float m = q[hh * 8];
#pragma unroll
        for (int j = 1; j < 8; j++) m = fmaxf(m, q[hh * 8 + j]);
        float s = 0.0f;
#pragma unroll
        for (int j = 0; j < 8; j++) {
            float v = __expf(q[hh * 8 + j] - m);
            q[hh * 8 + j] = v; s += v;
        }
        float inv = 1.0f / s, ub = 0.0f;
#pragma unroll
        for (int j = 0; j < 8; j++) {
            q[hh * 8 + j] *= inv;
            ub += q[hh * 8 + j] * sCM[c0 + hh * 8 + j];
        }
        heavy |= (ub > BIASF);
    }

    if (!__syncthreads_or(heavy)) {
        // FAST PATH: relu(k.q - BIAS) == 0 for every (user, head) in this tile
        //   => att = 0 => out = I + reproj_b (exact). Coalesced float4 stores.
        float4* op = (float4*)(out + (size_t)item * KC + c0);
#pragma unroll
        for (int i = 0; i < 4; i++)
            op[i] = make_float4(e[c0+4*i+0] + sRb[c0+4*i+0],
                                e[c0+4*i+1] + sRb[c0+4*i+1],
                                e[c0+4*i+2] + sRb[c0+4*i+2],
                                e[c0+4*i+3] + sRb[c0+4*i+3]);
        return;
    }

    // ---------------- SLOW PATH (block-uniform honest fallback) -------------
    {
        __shared__ float sKT[KC][D];     // transposed key weights
        __shared__ float sKb[KC];
        __shared__ float sU[RPB][D];
        __shared__ float sK[RPB][KC];

        for (int i = t; i < D * KC; i += NT) sKT[i & 31][i >> 5] = Kw[i];
        if (t < KC) sKb[t] = Kb[t];
        __syncthreads();

        float att[2][D];                  // this thread's 2 heads
#pragma unroll
        for (int hh = 0; hh < 2; hh++)
#pragma unroll
            for (int d = 0; d < D; d++) att[hh][d] = 0.0f;

        for (int u0 = 0; u0 < NU; u0 += RPB) {
            for (int i = t; i < RPB * D; i += NT)
                sU[i >> 5][i & 31] = U[(size_t)u0 * D + i];
            __syncthreads();
            {
                const int rr = t >> 1;
                float uu[D];
#pragma unroll
                for (int d = 0; d < D; d++) uu[d] = sU[rr][d];
#pragma unroll
                for (int cc = 0; cc < 16; cc++) {
                    const int c = c0 + cc;
                    float acc = sKb[c];
#pragma unroll
                    for (int d = 0; d < D; d++) acc = fmaf(uu[d], sKT[c][d], acc);
                    sK[rr][c] = __expf(acc) * sIZ[c];
                }
            }
            __syncthreads();
            for (int uu = 0; uu < RPB; uu++) {
#pragma unroll
                for (int hh = 0; hh < 2; hh++) {
                    float dot = 0.0f;
#pragma unroll
                    for (int j = 0; j < 8; j++)
                        dot += sK[uu][c0 + hh * 8 + j] * q[hh * 8 + j];
                    float w = dot - BIASF;
                    if (w > 0.0f) {
#pragma unroll
                        for (int d = 0; d < D; d++) att[hh][d] += w * sU[uu][d];
                    }
                }
            }
            __syncthreads();
        }

        // reprojection partials: this thread covers agg rows m = half*64 .. +63
        float o[D];
#pragma unroll
        for (int j = 0; j < D; j++) o[j] = (half == 0) ? sRb[j] : 0.0f;
        for (int mm = 0; mm < 64; mm++) {
            const int m = half * 64 + mm;          // global agg index h*32+d
            const float a = att[mm >> 5][mm & 31];
#pragma unroll
            for (int j = 0; j < D; j++) o[j] = fmaf(a, Rw[m * KC + j], o[j]);
        }
        // partner (lane^1) holds the other two heads' contribution
#pragma unroll
        for (int j = 0; j < D; j++) o[j] += __shfl_xor_sync(0xffffffffu, o[j], 1);
#pragma unroll
        for (int j = 0; j < 16; j++)
            out[(size_t)item * KC + c0 + j] = e[c0 + j] + o[c0 + j];
    }
}

// ---------------------------------------------------------------------------
extern "C" void kernel_launch(void* const* d_in, const int* in_sizes, int n_in,
                              void* d_out, int out_size)
{
    (void)in_sizes; (void)n_in; (void)out_size;
    const float* U  = (const float*)d_in[0];
    const float* I  = (const float*)d_in[1];
    const float* Kw = (const float*)d_in[2];
    const float* Kb = (const float*)d_in[3];
    const float* Qw = (const float*)d_in[4];
    const float* Qb = (const float*)d_in[5];
    const float* Rw = (const float*)d_in[6];
    const float* Rb = (const float*)d_in[7];
    float* out = (float*)d_out;

    k_keys<<<NB, NT>>>(U, Kw, Kb);
    k_items<<<NB, NT>>>(I, Qw, Qb, U, Kw, Kb, Rw, Rb, out);
}